// round 1
// baseline (speedup 1.0000x reference)
#include <cuda_runtime.h>
#include <math.h>

#define NT   32768
#define DIMS 512
#define KC   4096

// Scratch (no device mallocs allowed)
__device__ float  g_Sz[NT];
__device__ int    g_best[NT];
__device__ int    g_counts[KC];
__device__ double g_loss;

// ---------------------------------------------------------------------------
// Zero per-launch accumulators (graph replays must be deterministic).
// ---------------------------------------------------------------------------
__global__ void k_init() {
    int t = blockIdx.x * blockDim.x + threadIdx.x;
    if (t < KC) g_counts[t] = 0;
    if (t == 0) g_loss = 0.0;
}

// ---------------------------------------------------------------------------
// Row norms of z, fp64 accumulated then rounded to fp32.
// One warp per row; 8 rows per 256-thread block.
// ---------------------------------------------------------------------------
__global__ void k_znorm(const float* __restrict__ z) {
    int row  = blockIdx.x * 8 + (threadIdx.x >> 5);
    int lane = threadIdx.x & 31;
    const float* zr = z + (size_t)row * DIMS;
    double s = 0.0;
    #pragma unroll
    for (int i = 0; i < DIMS / 32; i++) {
        float v = zr[lane + 32 * i];
        s += (double)v * (double)v;
    }
    #pragma unroll
    for (int o = 16; o; o >>= 1) s += __shfl_down_sync(0xffffffffu, s, o);
    if (lane == 0) g_Sz[row] = (float)s;
}

// ---------------------------------------------------------------------------
// Fused SGEMM (z @ emb^T) + argmin epilogue.
// Tile: 128 tokens x 128 codes x k8, 256 threads, 8x8 per thread,
// double-buffered shared memory. Each block owns 128 token rows and scans
// ALL 4096 codes, so the argmin finishes block-locally (no cross-block
// reduction). Distance replicates the reference rounding:
//   d = fl32(Sz - 2*fl32(z.e))   (the ||e||^2 term is provably absorbed
//   by fp32 rounding at magnitude ~512: ||e||^2 <= 1.16e-5 < half-ulp).
// Ties broken by lowest code index at every level.
// ---------------------------------------------------------------------------
__global__ __launch_bounds__(256, 2) void k_gemm_argmin(
        const float* __restrict__ z, const float* __restrict__ emb) {
    __shared__ float As[2][8][128];
    __shared__ float Bs[2][8][128];

    const int tid  = threadIdx.x;
    const int m0   = blockIdx.x * 128;
    const int tr   = tid >> 4;        // 0..15 : token sub-tile
    const int tc   = tid & 15;        // 0..15 : code  sub-tile
    const int lrow = tid >> 1;        // 0..127: load row
    const int lseg = (tid & 1) * 4;   // 0 or 4: load segment

    const float* zp = z + (size_t)(m0 + lrow) * DIMS + lseg;

    float Szr[8];
    #pragma unroll
    for (int i = 0; i < 8; i++) Szr[i] = g_Sz[m0 + tr * 8 + i];

    float bv[8]; int bi[8];
    #pragma unroll
    for (int i = 0; i < 8; i++) { bv[i] = __int_as_float(0x7f800000); bi[i] = 0; }

    for (int n0 = 0; n0 < KC; n0 += 128) {
        const float* ep = emb + (size_t)(n0 + lrow) * DIMS + lseg;

        float acc[8][8];
        #pragma unroll
        for (int i = 0; i < 8; i++)
            #pragma unroll
            for (int j = 0; j < 8; j++) acc[i][j] = 0.0f;

        // prime buffer 0
        {
            float4 a = *(const float4*)zp;
            float4 b = *(const float4*)ep;
            As[0][lseg + 0][lrow] = a.x; As[0][lseg + 1][lrow] = a.y;
            As[0][lseg + 2][lrow] = a.z; As[0][lseg + 3][lrow] = a.w;
            Bs[0][lseg + 0][lrow] = b.x; Bs[0][lseg + 1][lrow] = b.y;
            Bs[0][lseg + 2][lrow] = b.z; Bs[0][lseg + 3][lrow] = b.w;
        }
        __syncthreads();

        int cur = 0;
        for (int k0 = 0; k0 < DIMS; k0 += 8) {
            float4 a2, b2;
            const bool has = (k0 + 8) < DIMS;
            if (has) {                       // global prefetch into regs
                a2 = *(const float4*)(zp + k0 + 8);
                b2 = *(const float4*)(ep + k0 + 8);
            }
            #pragma unroll
            for (int kk = 0; kk < 8; kk++) {
                float ra[8], rb[8];
                *(float4*)&ra[0] = *(const float4*)&As[cur][kk][tr * 8];
                *(float4*)&ra[4] = *(const float4*)&As[cur][kk][tr * 8 + 4];
                *(float4*)&rb[0] = *(const float4*)&Bs[cur][kk][tc * 8];
                *(float4*)&rb[4] = *(const float4*)&Bs[cur][kk][tc * 8 + 4];
                #pragma unroll
                for (int i = 0; i < 8; i++)
                    #pragma unroll
                    for (int j = 0; j < 8; j++)
                        acc[i][j] = fmaf(ra[i], rb[j], acc[i][j]);
            }
            if (has) {
                const int nxt = cur ^ 1;
                As[nxt][lseg + 0][lrow] = a2.x; As[nxt][lseg + 1][lrow] = a2.y;
                As[nxt][lseg + 2][lrow] = a2.z; As[nxt][lseg + 3][lrow] = a2.w;
                Bs[nxt][lseg + 0][lrow] = b2.x; Bs[nxt][lseg + 1][lrow] = b2.y;
                Bs[nxt][lseg + 2][lrow] = b2.z; Bs[nxt][lseg + 3][lrow] = b2.w;
            }
            __syncthreads();
            cur ^= 1;
        }

        // argmin epilogue over this 128-code tile
        #pragma unroll
        for (int i = 0; i < 8; i++) {
            float mv = __fmaf_rn(-2.0f, acc[i][0], Szr[i]);
            int   mj = 0;
            #pragma unroll
            for (int j = 1; j < 8; j++) {
                float v = __fmaf_rn(-2.0f, acc[i][j], Szr[i]);
                if (v < mv) { mv = v; mj = j; }  // strict <: keep first index
            }
            int gi = n0 + tc * 8 + mj;
            #pragma unroll
            for (int off = 8; off; off >>= 1) {  // reduce across 16 code lanes
                float ov = __shfl_down_sync(0xffffffffu, mv, off, 16);
                int   oi = __shfl_down_sync(0xffffffffu, gi, off, 16);
                if (ov < mv || (ov == mv && oi < gi)) { mv = ov; gi = oi; }
            }
            if (tc == 0) {
                if (mv < bv[i] || (mv == bv[i] && gi < bi[i])) {
                    bv[i] = mv; bi[i] = gi;
                }
            }
        }
    }

    if (tc == 0) {
        #pragma unroll
        for (int i = 0; i < 8; i++) g_best[m0 + tr * 8 + i] = bi[i];
    }
}

// ---------------------------------------------------------------------------
// Gather + straight-through output + loss accumulation + histogram.
// out = fl(z + fl(q - z)) exactly as the reference computes it (intrinsics
// prevent fast-math from folding this to q).
// ---------------------------------------------------------------------------
__global__ void k_gather(const float* __restrict__ z,
                         const float* __restrict__ emb,
                         float* __restrict__ out) {
    const int row = blockIdx.x;
    const int idx = g_best[row];
    const float* zr = z   + (size_t)row * DIMS;
    const float* er = emb + (size_t)idx * DIMS;
    float* orow = out + (size_t)row * DIMS;

    double s = 0.0;
    for (int i = threadIdx.x; i < DIMS; i += blockDim.x) {
        float q  = er[i];
        float zz = zr[i];
        float t  = __fsub_rn(q, zz);
        orow[i]  = __fadd_rn(zz, t);
        s += (double)t * (double)t;
    }

    __shared__ double sh[4];
    #pragma unroll
    for (int o = 16; o; o >>= 1) s += __shfl_down_sync(0xffffffffu, s, o);
    if ((threadIdx.x & 31) == 0) sh[threadIdx.x >> 5] = s;
    __syncthreads();
    if (threadIdx.x == 0) {
        double tot = sh[0] + sh[1] + sh[2] + sh[3];
        atomicAdd(&g_loss, tot);
        atomicAdd(&g_counts[idx], 1);
    }
}

// ---------------------------------------------------------------------------
// Scalars: vq_loss = 1.25 * mean((q-z)^2), perplexity = exp(-sum p log(p+1e-10))
// ---------------------------------------------------------------------------
__global__ void k_final(float* __restrict__ out, int loss_pos) {
    __shared__ double sh[8];
    const int tid = threadIdx.x;
    double h = 0.0;
    for (int i = tid; i < KC; i += 256) {
        double p = (double)g_counts[i] / (double)NT;  // exact: /2^15
        h += p * log(p + 1e-10);
    }
    #pragma unroll
    for (int o = 16; o; o >>= 1) h += __shfl_down_sync(0xffffffffu, h, o);
    if ((tid & 31) == 0) sh[tid >> 5] = h;
    __syncthreads();
    if (tid == 0) {
        double t = 0.0;
        #pragma unroll
        for (int w = 0; w < 8; w++) t += sh[w];
        double mean = g_loss / ((double)NT * (double)DIMS);
        out[loss_pos]     = (float)(1.25 * mean);
        out[loss_pos + 1] = (float)exp(-t);
    }
}

// ---------------------------------------------------------------------------
extern "C" void kernel_launch(void* const* d_in, const int* in_sizes, int n_in,
                              void* d_out, int out_size) {
    const float* z   = (const float*)d_in[0];
    const float* emb = (const float*)d_in[1];
    // defensive: identify tensors by size (z: 32768*512, emb: 4096*512)
    if (n_in >= 2 && in_sizes[0] == KC * DIMS && in_sizes[1] == NT * DIMS) {
        z   = (const float*)d_in[1];
        emb = (const float*)d_in[0];
    }
    float* out = (float*)d_out;

    k_init<<<16, 256>>>();
    k_znorm<<<NT / 8, 256>>>(z);
    k_gemm_argmin<<<NT / 128, 256>>>(z, emb);
    k_gather<<<NT, 128>>>(z, emb, out);
    k_final<<<1, 256>>>(out, out_size - 2);
}

// round 4
// speedup vs baseline: 5.2171x; 5.2171x over previous
#include <cuda_runtime.h>
#include <cuda_fp16.h>
#include <math.h>
#include <stdint.h>

#define NT   32768
#define DIMS 512
#define KC   4096

#define M_TILE 128
#define N_TILE 256
#define BK     64
#define NITER  ((KC / N_TILE) * (DIMS / BK))   // 16 * 8 = 128
#define MARGIN 2.5e-4f
#define MAXCAND 32

// SMEM stage: A 128x64 fp16 (16KB) + B 256x64 fp16 (32KB) = 48KB; 2 stages.
#define SA_OFF   0
#define SB_OFF   16384
#define STG      49152
#define SM_SCR   (2 * STG)            // smin(512) + scnt(512)
#define SM_TOTAL (SM_SCR + 1024)      // 99328

// ---------------- scratch (device globals; no mallocs allowed) ----------------
__device__ float   g_Sz[NT];
__device__ int     g_best[NT];
__device__ int     g_counts[KC];
__device__ double  g_loss;
__device__ __half  g_z1[NT * DIMS];
__device__ __half  g_e1[KC * DIMS];
__device__ int     g_cand[NT * MAXCAND];
__device__ int     g_ccount[NT];

// ---------------- PTX helpers (compute_103-safe) ----------------
__device__ __forceinline__ uint32_t smem_u32(const void* p) {
    uint32_t a;
    asm("{ .reg .u64 t; cvta.to.shared.u64 t, %1; cvt.u32.u64 %0, t; }" : "=r"(a) : "l"(p));
    return a;
}
__device__ __forceinline__ void cp16(uint32_t dst, const void* src) {
    asm volatile("cp.async.cg.shared.global [%0], [%1], 16;" :: "r"(dst), "l"(src) : "memory");
}
#define CP_COMMIT() asm volatile("cp.async.commit_group;" ::: "memory")
#define CP_WAIT(n)  asm volatile("cp.async.wait_group %0;" :: "n"(n) : "memory")

__device__ __forceinline__ void ldsm4(uint32_t* r, uint32_t addr) {
    asm volatile("ldmatrix.sync.aligned.m8n8.x4.shared.b16 {%0,%1,%2,%3}, [%4];"
                 : "=r"(r[0]), "=r"(r[1]), "=r"(r[2]), "=r"(r[3]) : "r"(addr));
}
__device__ __forceinline__ void mma16816(float* d, const uint32_t* a,
                                         uint32_t b0, uint32_t b1) {
    asm volatile(
        "mma.sync.aligned.m16n8k16.row.col.f32.f16.f16.f32 "
        "{%0,%1,%2,%3}, {%4,%5,%6,%7}, {%8,%9}, {%0,%1,%2,%3};"
        : "+f"(d[0]), "+f"(d[1]), "+f"(d[2]), "+f"(d[3])
        : "r"(a[0]), "r"(a[1]), "r"(a[2]), "r"(a[3]), "r"(b0), "r"(b1));
}

// ---------------------------------------------------------------------------
__global__ void k_init() {
    int t = blockIdx.x * blockDim.x + threadIdx.x;
    if (t < KC) g_counts[t] = 0;
    if (t == 0) g_loss = 0.0;
}

// Row norms of z in fp64, rounded to fp32 (R1-verified numerics).
__global__ void k_znorm(const float* __restrict__ z) {
    int row  = blockIdx.x * 8 + (threadIdx.x >> 5);
    int lane = threadIdx.x & 31;
    const float* zr = z + (size_t)row * DIMS;
    double s = 0.0;
    #pragma unroll
    for (int i = 0; i < DIMS / 32; i++) {
        float v = zr[lane + 32 * i];
        s += (double)v * (double)v;
    }
    #pragma unroll
    for (int o = 16; o; o >>= 1) s += __shfl_down_sync(0xffffffffu, s, o);
    if (lane == 0) g_Sz[row] = (float)s;
}

// fp32 -> fp16 (rn), 8 elems/thread.
__global__ void k_cvt16(const float* __restrict__ x, __half* __restrict__ y, int n8) {
    int i = blockIdx.x * blockDim.x + threadIdx.x;
    if (i >= n8) return;
    float4 a = ((const float4*)x)[i * 2 + 0];
    float4 b = ((const float4*)x)[i * 2 + 1];
    uint4 o;
    __half2 p;
    p = __halves2half2(__float2half_rn(a.x), __float2half_rn(a.y)); o.x = *(uint32_t*)&p;
    p = __halves2half2(__float2half_rn(a.z), __float2half_rn(a.w)); o.y = *(uint32_t*)&p;
    p = __halves2half2(__float2half_rn(b.x), __float2half_rn(b.y)); o.z = *(uint32_t*)&p;
    p = __halves2half2(__float2half_rn(b.z), __float2half_rn(b.w)); o.w = *(uint32_t*)&p;
    ((uint4*)y)[i] = o;
}

// ---------------------------------------------------------------------------
// fp16 mma.sync approx-distance GEMM + candidate capture.
// CTA: 128 tokens x all 4096 codes; 8 warps as 2(m) x 4(n), warp tile 64x64.
// Per n-tile of 256 codes: running min (SMEM, atomicMin on positive-float bits)
// then margin-append candidates to g_cand. True argmin provably in the set.
// ---------------------------------------------------------------------------
__global__ __launch_bounds__(256, 1) void k_vq_mma() {
    extern __shared__ char smem[];
    const uint32_t sb = smem_u32(smem);
    int*  smin = (int*)(smem + SM_SCR);
    int*  scnt = (int*)(smem + SM_SCR + 512);
    const int tid  = threadIdx.x;
    const int lane = tid & 31;
    const int wid  = tid >> 5;
    const int wm   = wid >> 2;     // 0..1 (m)
    const int wn   = wid & 3;      // 0..3 (n)
    const int m0   = blockIdx.x * M_TILE;

    const __half* __restrict__ zb = g_z1;
    const __half* __restrict__ eb = g_e1;

    if (tid < 128) { smin[tid] = 0x7f800000; scnt[tid] = 0; }

    // prologue: issue stages 0,1
    #pragma unroll
    for (int t0 = 0; t0 < 2; t0++) {
        const int n0 = (t0 >> 3) * N_TILE, ko = (t0 & 7) * BK;
        const uint32_t sd = sb + (uint32_t)(t0 & 1) * STG;
        #pragma unroll
        for (int i = 0; i < 4; i++) {           // A: 128 rows x 4 chunks... 1024 total
            int q = i * 256 + tid;
            int row = q >> 3, c = q & 7;
            cp16(sd + SA_OFF + (uint32_t)(row * 128 + ((c ^ (row & 7)) * 16)),
                 zb + (size_t)(m0 + row) * DIMS + ko + c * 8);
        }
        #pragma unroll
        for (int i = 0; i < 8; i++) {           // B: 256 rows x 8 chunks
            int q = i * 256 + tid;
            int row = q >> 3, c = q & 7;
            cp16(sd + SB_OFF + (uint32_t)(row * 128 + ((c ^ (row & 7)) * 16)),
                 eb + (size_t)(n0 + row) * DIMS + ko + c * 8);
        }
        CP_COMMIT();
    }

    // ldmatrix lane geometry (R3-validated)
    const int rA  = wm * 64 + ((lane >> 3) & 1) * 8 + (lane & 7);
    const int khA = lane >> 4;                 // 0..1
    const int rB0 = wn * 64 + ((lane >> 4) & 1) * 8 + (lane & 7);
    const int khB = (lane >> 3) & 1;

    float Szr[4][2];
    #pragma unroll
    for (int mi = 0; mi < 4; mi++)
        #pragma unroll
        for (int rh = 0; rh < 2; rh++)
            Szr[mi][rh] = g_Sz[m0 + wm * 64 + mi * 16 + (lane >> 2) + rh * 8];

    float acc[4][8][4];

    for (int t = 0; t < NITER; t++) {
        if (t < NITER - 1) CP_WAIT(1); else CP_WAIT(0);
        __syncthreads();

        const uint32_t sd = sb + (uint32_t)(t & 1) * STG;

        if ((t & 7) == 0) {
            #pragma unroll
            for (int mi = 0; mi < 4; mi++)
                #pragma unroll
                for (int ni = 0; ni < 8; ni++)
                    #pragma unroll
                    for (int r = 0; r < 4; r++) acc[mi][ni][r] = 0.0f;
        }

        #pragma unroll
        for (int kk = 0; kk < 4; kk++) {
            uint32_t af[4][4];
            const int cA = kk * 2 + khA;
            #pragma unroll
            for (int mi = 0; mi < 4; mi++) {
                const int r = rA + mi * 16;
                ldsm4(af[mi], sd + SA_OFF + (uint32_t)(r * 128 + ((cA ^ (r & 7)) * 16)));
            }
            uint32_t bf[4][4];
            const int cB = kk * 2 + khB;
            #pragma unroll
            for (int nn = 0; nn < 4; nn++) {
                const int r = rB0 + nn * 16;
                ldsm4(bf[nn], sd + SB_OFF + (uint32_t)(r * 128 + ((cB ^ (r & 7)) * 16)));
            }
            #pragma unroll
            for (int mi = 0; mi < 4; mi++)
                #pragma unroll
                for (int ni = 0; ni < 8; ni++)
                    mma16816(acc[mi][ni], af[mi],
                             bf[ni >> 1][(ni & 1) * 2], bf[ni >> 1][(ni & 1) * 2 + 1]);
        }

        // candidate-capture epilogue when this 256-code tile's K is complete
        if ((t & 7) == 7) {
            const int n0g = (t >> 3) * N_TILE;
            // phase 1: update running min per token
            #pragma unroll
            for (int mi = 0; mi < 4; mi++)
                #pragma unroll
                for (int rh = 0; rh < 2; rh++) {
                    float m = __int_as_float(0x7f800000);
                    #pragma unroll
                    for (int ni = 0; ni < 8; ni++)
                        #pragma unroll
                        for (int cc = 0; cc < 2; cc++) {
                            float v = __fmaf_rn(-2.0f, acc[mi][ni][rh * 2 + cc],
                                                Szr[mi][rh]);
                            m = fminf(m, v);
                        }
                    int rl = wm * 64 + mi * 16 + (lane >> 2) + rh * 8;
                    atomicMin(&smin[rl], __float_as_int(m));
                }
            __syncthreads();
            // phase 2: append codes within margin of running min
            #pragma unroll
            for (int mi = 0; mi < 4; mi++)
                #pragma unroll
                for (int rh = 0; rh < 2; rh++) {
                    int rl = wm * 64 + mi * 16 + (lane >> 2) + rh * 8;
                    float thr = __int_as_float(smin[rl]) + MARGIN;
                    #pragma unroll
                    for (int ni = 0; ni < 8; ni++)
                        #pragma unroll
                        for (int cc = 0; cc < 2; cc++) {
                            float v = __fmaf_rn(-2.0f, acc[mi][ni][rh * 2 + cc],
                                                Szr[mi][rh]);
                            if (v < thr) {
                                int s = atomicAdd(&scnt[rl], 1);
                                if (s < MAXCAND)
                                    g_cand[(size_t)(m0 + rl) * MAXCAND + s] =
                                        n0g + wn * 64 + ni * 8 + (lane & 3) * 2 + cc;
                            }
                        }
                }
        }

        __syncthreads();
        if (t + 2 < NITER) {
            const int t2 = t + 2;
            const int n0 = (t2 >> 3) * N_TILE, ko = (t2 & 7) * BK;
            const uint32_t sd2 = sb + (uint32_t)(t2 & 1) * STG;
            #pragma unroll
            for (int i = 0; i < 4; i++) {
                int q = i * 256 + tid;
                int row = q >> 3, c = q & 7;
                cp16(sd2 + SA_OFF + (uint32_t)(row * 128 + ((c ^ (row & 7)) * 16)),
                     zb + (size_t)(m0 + row) * DIMS + ko + c * 8);
            }
            #pragma unroll
            for (int i = 0; i < 8; i++) {
                int q = i * 256 + tid;
                int row = q >> 3, c = q & 7;
                cp16(sd2 + SB_OFF + (uint32_t)(row * 128 + ((c ^ (row & 7)) * 16)),
                     eb + (size_t)(n0 + row) * DIMS + ko + c * 8);
            }
            CP_COMMIT();
        }
    }

    __syncthreads();
    if (tid < 128) g_ccount[m0 + tid] = scnt[tid];
}

// ---------------------------------------------------------------------------
// Exact fp32 refinement: warp per token, evaluate candidates, lexicographic
// (distance, index) min — reproduces the reference argmin + tie-breaking.
// Overflowed tokens (count > MAXCAND, ~never) rescan all 4096 codes.
// ---------------------------------------------------------------------------
__global__ void k_refine(const float* __restrict__ z, const float* __restrict__ emb) {
    const int row  = blockIdx.x * 8 + (threadIdx.x >> 5);
    const int lane = threadIdx.x & 31;
    const int cnt  = g_ccount[row];
    const float Sz = g_Sz[row];

    float zr[16];
    const float* zp = z + (size_t)row * DIMS;
    #pragma unroll
    for (int i = 0; i < 16; i++) zr[i] = zp[lane + 32 * i];

    const bool ovf = (cnt > MAXCAND);
    const int n = ovf ? KC : cnt;
    float bv = __int_as_float(0x7f800000);
    int   bi = 0;

    for (int j = 0; j < n; j++) {
        int c = ovf ? j : g_cand[(size_t)row * MAXCAND + j];
        const float* er = emb + (size_t)c * DIMS;
        float s = 0.0f;
        #pragma unroll
        for (int i = 0; i < 16; i++) s = __fmaf_rn(zr[i], er[lane + 32 * i], s);
        #pragma unroll
        for (int o = 16; o; o >>= 1) s += __shfl_xor_sync(0xffffffffu, s, o);
        float d = __fmaf_rn(-2.0f, s, Sz);
        if (d < bv || (d == bv && c < bi)) { bv = d; bi = c; }
    }
    if (lane == 0) g_best[row] = bi;
}

// ---------------------------------------------------------------------------
// Gather + straight-through output + loss + histogram. Warp per row.
// ---------------------------------------------------------------------------
__global__ void k_gather(const float* __restrict__ z,
                         const float* __restrict__ emb,
                         float* __restrict__ out) {
    const int warp = threadIdx.x >> 5;
    const int lane = threadIdx.x & 31;
    const int row  = blockIdx.x * 8 + warp;
    const int idx  = g_best[row];

    const float4* zr = (const float4*)(z   + (size_t)row * DIMS);
    const float4* er = (const float4*)(emb + (size_t)idx * DIMS);
    float4* orow = (float4*)(out + (size_t)row * DIMS);

    double s = 0.0;
    #pragma unroll
    for (int j = 0; j < 4; j++) {
        float4 q  = er[lane + 32 * j];
        float4 zz = zr[lane + 32 * j];
        float4 o;
        float t;
        t = __fsub_rn(q.x, zz.x); o.x = __fadd_rn(zz.x, t); s += (double)t * t;
        t = __fsub_rn(q.y, zz.y); o.y = __fadd_rn(zz.y, t); s += (double)t * t;
        t = __fsub_rn(q.z, zz.z); o.z = __fadd_rn(zz.z, t); s += (double)t * t;
        t = __fsub_rn(q.w, zz.w); o.w = __fadd_rn(zz.w, t); s += (double)t * t;
        orow[lane + 32 * j] = o;
    }
    #pragma unroll
    for (int o = 16; o; o >>= 1) s += __shfl_down_sync(0xffffffffu, s, o);

    __shared__ double sh[8];
    if (lane == 0) {
        sh[warp] = s;
        atomicAdd(&g_counts[idx], 1);
    }
    __syncthreads();
    if (threadIdx.x == 0) {
        double tot = 0.0;
        #pragma unroll
        for (int w = 0; w < 8; w++) tot += sh[w];
        atomicAdd(&g_loss, tot);
    }
}

__global__ void k_final(float* __restrict__ out, int loss_pos) {
    __shared__ double sh[8];
    const int tid = threadIdx.x;
    double h = 0.0;
    for (int i = tid; i < KC; i += 256) {
        double p = (double)g_counts[i] / (double)NT;
        h += p * log(p + 1e-10);
    }
    #pragma unroll
    for (int o = 16; o; o >>= 1) h += __shfl_down_sync(0xffffffffu, h, o);
    if ((tid & 31) == 0) sh[tid >> 5] = h;
    __syncthreads();
    if (tid == 0) {
        double t = 0.0;
        #pragma unroll
        for (int w = 0; w < 8; w++) t += sh[w];
        double mean = g_loss / ((double)NT * (double)DIMS);
        out[loss_pos]     = (float)(1.25 * mean);
        out[loss_pos + 1] = (float)exp(-t);
    }
}

// ---------------------------------------------------------------------------
extern "C" void kernel_launch(void* const* d_in, const int* in_sizes, int n_in,
                              void* d_out, int out_size) {
    const float* z   = (const float*)d_in[0];
    const float* emb = (const float*)d_in[1];
    if (n_in >= 2 && in_sizes[0] == KC * DIMS && in_sizes[1] == NT * DIMS) {
        z   = (const float*)d_in[1];
        emb = (const float*)d_in[0];
    }
    float* out = (float*)d_out;

    cudaFuncSetAttribute(k_vq_mma, cudaFuncAttributeMaxDynamicSharedMemorySize,
                         SM_TOTAL);

    __half *z1, *e1;
    cudaGetSymbolAddress((void**)&z1, g_z1);
    cudaGetSymbolAddress((void**)&e1, g_e1);

    k_init<<<16, 256>>>();
    k_znorm<<<NT / 8, 256>>>(z);
    k_cvt16<<<(NT * DIMS / 8) / 256, 256>>>(z, z1, NT * DIMS / 8);
    k_cvt16<<<(KC * DIMS / 8) / 256, 256>>>(emb, e1, KC * DIMS / 8);
    k_vq_mma<<<NT / M_TILE, 256, SM_TOTAL>>>();
    k_refine<<<NT / 8, 256>>>(z, emb);
    k_gather<<<NT / 8, 256>>>(z, emb, out);
    k_final<<<1, 256>>>(out, out_size - 2);
}